// round 11
// baseline (speedup 1.0000x reference)
#include <cuda_runtime.h>
#include <cuda_fp16.h>
#include <math.h>
#include <stdint.h>

// ---------------------------------------------------------------------------
// Problem constants
// ---------------------------------------------------------------------------
#define BATCH 4
#define NBATCH 8            // outputs(0-3) + styles(4-7) fused
#define FEAT_C 768
#define FEAT_N 4096
#define EPS 1e-8f

// ---------------------------------------------------------------------------
// Device scratch. NHWC hi/lo fp16 activation planes.
// ---------------------------------------------------------------------------
#define ACT_ELEMS (NBATCH * 256 * 256 * 64)
__device__ __align__(128) __half g_Ah[ACT_ELEMS];
__device__ __align__(128) __half g_Al[ACT_ELEMS];
__device__ __align__(128) __half g_Bh[ACT_ELEMS];
__device__ __align__(128) __half g_Bl[ACT_ELEMS];
__device__ __align__(128) __half g_feath[NBATCH * FEAT_N * FEAT_C];
__device__ __align__(128) __half g_featl[NBATCH * FEAT_N * FEAT_C];
// Winograd-transformed fragment-ordered weights: 16 pos x Co x Ci per layer
#define UPOOL_ELEMS 3080192
__device__ __align__(128) __half g_uh[UPOOL_ELEMS];
__device__ __align__(128) __half g_ul[UPOOL_ELEMS];
__device__ __align__(128) float  g_xn[NBATCH * FEAT_N * FEAT_C];
__device__ __align__(128) __half g_xh[NBATCH * FEAT_N * FEAT_C];
__device__ float g_rnorm[NBATCH * FEAT_N];
__device__ float g_rowmax[BATCH * FEAT_N];
__device__ int2  g_cand[BATCH * FEAT_N];

// U pool offsets (halves)
#define U12_OFF 0         // 16*64*64
#define U21_OFF 65536     // 16*128*64
#define U22_OFF 196608    // 16*128*128
#define U31_OFF 458752    // 16*256*128
#define U32_OFF 983040    // 16*256*256
#define U33_OFF 2031616   // 16*256*256

// ---------------------------------------------------------------------------
// mma.sync helpers (verified)
// ---------------------------------------------------------------------------
__device__ __forceinline__ uint32_t smem_addr32(const void* p) {
    return (uint32_t)__cvta_generic_to_shared(p);
}
__device__ __forceinline__ void ldm_x4(uint32_t addr, uint32_t r[4]) {
    asm volatile("ldmatrix.sync.aligned.m8n8.x4.shared.b16 {%0,%1,%2,%3}, [%4];"
                 : "=r"(r[0]), "=r"(r[1]), "=r"(r[2]), "=r"(r[3]) : "r"(addr));
}
__device__ __forceinline__ void mma16816(float d[4], const uint32_t a[4],
                                         uint32_t b0, uint32_t b1) {
    asm volatile(
        "mma.sync.aligned.m16n8k16.row.col.f32.f16.f16.f32 "
        "{%0,%1,%2,%3}, {%4,%5,%6,%7}, {%8,%9}, {%0,%1,%2,%3};"
        : "+f"(d[0]), "+f"(d[1]), "+f"(d[2]), "+f"(d[3])
        : "r"(a[0]), "r"(a[1]), "r"(a[2]), "r"(a[3]), "r"(b0), "r"(b1));
}
__device__ __forceinline__ void cp_async16(uint32_t saddr, const void* gaddr, int srcsz) {
    asm volatile("cp.async.ca.shared.global [%0], [%1], 16, %2;"
                 :: "r"(saddr), "l"(gaddr), "r"(srcsz));
}

// ---------------------------------------------------------------------------
// Winograd weight prep: U = G g G^T per (oc, ic), hi/lo split,
// fragment-ordered [pos][oc16][ic16] tiles of 128 u32 (verified (j,lane) map).
// ---------------------------------------------------------------------------
__global__ void uprep_kernel(const float* __restrict__ w, __half* __restrict__ uh,
                             __half* __restrict__ ul, int Cout, int Cin) {
    uint32_t* uhu = (uint32_t*)uh;
    uint32_t* ulu = (uint32_t*)ul;
    int co16 = Cout >> 4, ci16 = Cin >> 4;
    int total = Cout * (Cin >> 1);
    for (int i = blockIdx.x * blockDim.x + threadIdx.x; i < total;
         i += gridDim.x * blockDim.x) {
        int oc = i / (Cin >> 1);
        int ic = (i - oc * (Cin >> 1)) * 2;
        float U[2][4][4];
#pragma unroll
        for (int s = 0; s < 2; s++) {
            const float* g = w + ((long)oc * Cin + ic + s) * 9;
            float t[4][3];
#pragma unroll
            for (int c = 0; c < 3; c++) {
                float g0 = g[c], g1 = g[3 + c], g2 = g[6 + c];
                t[0][c] = g0;
                t[1][c] = 0.5f * (g0 + g1 + g2);
                t[2][c] = 0.5f * (g0 - g1 + g2);
                t[3][c] = g2;
            }
#pragma unroll
            for (int r = 0; r < 4; r++) {
                U[s][r][0] = t[r][0];
                U[s][r][1] = 0.5f * (t[r][0] + t[r][1] + t[r][2]);
                U[s][r][2] = 0.5f * (t[r][0] - t[r][1] + t[r][2]);
                U[s][r][3] = t[r][2];
            }
        }
        int ocl = oc & 15, icl = ic & 15;
        int j = ((ocl >> 3) << 1) | (icl >> 3);
        int lane = (ocl & 7) * 4 + ((icl & 7) >> 1);
#pragma unroll
        for (int pos = 0; pos < 16; pos++) {
            float v0 = U[0][pos >> 2][pos & 3];
            float v1 = U[1][pos >> 2][pos & 3];
            __half h0 = __float2half(v0), h1 = __float2half(v1);
            __half l0 = __float2half(v0 - __half2float(h0));
            __half l1 = __float2half(v1 - __half2float(h1));
            __half2 hh = __halves2half2(h0, h1);
            __half2 ll = __halves2half2(l0, l1);
            long tidx = ((long)(pos * co16 + (oc >> 4))) * ci16 + (ic >> 4);
            uhu[tidx * 128 + lane * 4 + j] = *(uint32_t*)&hh;
            ulu[tidx * 128 + lane * 4 + j] = *(uint32_t*)&ll;
        }
    }
}

// ---------------------------------------------------------------------------
// conv1_1: fused normalize + 3->64 conv + bias + relu (batch 8)
// ---------------------------------------------------------------------------
__global__ __launch_bounds__(256)
void conv1_kernel(const float* __restrict__ imgA, const float* __restrict__ imgB,
                  const float* __restrict__ w, const float* __restrict__ bias,
                  __half* __restrict__ oh, __half* __restrict__ ol) {
    __shared__ float sw[64 * 27];
    __shared__ float sb[64];
    int tid = threadIdx.x;
    for (int i = tid; i < 64 * 27; i += 256) sw[i] = w[i];
    if (tid < 64) sb[tid] = bias[tid];
    __syncthreads();

    const float mean[3] = {0.485f, 0.456f, 0.406f};
    const float istd[3] = {1.f / 0.229f, 1.f / 0.224f, 1.f / 0.225f};

    int gid = blockIdx.x * 256 + tid;
    int b = gid >> 16;
    int y = (gid >> 8) & 255;
    int x = gid & 255;
    const float* base = (b < 4) ? imgA : imgB;
    int bb = b & 3;

    float in[3][9];
#pragma unroll
    for (int c = 0; c < 3; c++) {
        const float* ip = base + (((long)bb * 3 + c) << 16);
#pragma unroll
        for (int dy = 0; dy < 3; dy++)
#pragma unroll
            for (int dx = 0; dx < 3; dx++) {
                int gy = y + dy - 1, gx = x + dx - 1;
                float v = 0.f;
                if (gy >= 0 && gy < 256 && gx >= 0 && gx < 256)
                    v = (ip[(gy << 8) + gx] - mean[c]) * istd[c];
                in[c][dy * 3 + dx] = v;
            }
    }

    long obase = (long)gid * 64;
#pragma unroll 4
    for (int oc = 0; oc < 64; oc++) {
        float acc = sb[oc];
        const float* wp = &sw[oc * 27];
#pragma unroll
        for (int c = 0; c < 3; c++)
#pragma unroll
            for (int k = 0; k < 9; k++)
                acc = fmaf(in[c][k], wp[c * 9 + k], acc);
        acc = acc > 0.f ? acc : 0.f;
        __half h = __float2half(acc);
        oh[obase + oc] = h;
        ol[obase + oc] = __float2half(acc - __half2float(h));
    }
}

// ---------------------------------------------------------------------------
// Fused Winograd F(2x2,3x3) conv, split-fp16 (hh+hl+lh) GEMMs.
// CTA: 8x8 output px (16 tiles) x 64 oc. 8 warps x 2 Winograd positions.
// smem: halo [2buf][2pl][100px][24] @0 ; V [16pos][2pl][16tile][24] @9600
// epilogue aliases smem as M[16][16*64+1] fp32.
// ---------------------------------------------------------------------------
#define HALO_HALVES 2400
#define V_OFF 9600
#define V_PL 384
#define WINO_SMEM 65600

__global__ __launch_bounds__(256)
void conv_wino_kernel(const __half* __restrict__ inh, const __half* __restrict__ inl,
                      const __half* __restrict__ ufh, const __half* __restrict__ ufl,
                      const float* __restrict__ bias,
                      __half* __restrict__ outh, __half* __restrict__ outl,
                      int Cin, int Cout, int H, int W, int inStride, int outStride) {
    extern __shared__ __align__(16) __half dsm[];
    uint32_t s32 = smem_addr32(dsm);
    int tid = threadIdx.x, lane = tid & 31, wid = tid >> 5;
    int ocb = Cout >> 6;
    int b = blockIdx.z / ocb;
    int oc0 = (blockIdx.z % ocb) << 6;
    int ry0 = blockIdx.y * 8, rx0 = blockIdx.x * 8;
    int nk = Cin >> 4, co16 = Cout >> 4, ci16 = Cin >> 4;
    const uint4* ufh4 = (const uint4*)ufh;
    const uint4* ufl4 = (const uint4*)ufl;

    float d[2][8][4];
#pragma unroll
    for (int i = 0; i < 2; i++)
#pragma unroll
        for (int j = 0; j < 8; j++)
#pragma unroll
            for (int e = 0; e < 4; e++) d[i][j][e] = 0.f;

    auto stage = [&](int kc, int buf) {
        int icc = kc << 4;
        for (int u = tid; u < 400; u += 256) {
            int px = u >> 2;
            int seg = (u >> 1) & 1;
            int pl = u & 1;
            int r = px / 10, c = px - r * 10;
            int gy = ry0 - 1 + r, gx = rx0 - 1 + c;
            int valid = (gy >= 0 && gy < H && gx >= 0 && gx < W) ? 16 : 0;
            int gyc = gy < 0 ? 0 : (gy >= H ? H - 1 : gy);
            int gxc = gx < 0 ? 0 : (gx >= W ? W - 1 : gx);
            const __half* gp = (pl ? inl : inh)
                + ((long)(b * H + gyc) * W + gxc) * inStride + icc + seg * 8;
            uint32_t off = (uint32_t)((buf * 2 + pl) * HALO_HALVES + px * 24 + seg * 8);
            cp_async16(s32 + off * 2, gp, valid);
        }
        asm volatile("cp.async.commit_group;" ::: "memory");
    };

    stage(0, 0);

    for (int kc = 0; kc < nk; kc++) {
        int buf = kc & 1;
        if (kc + 1 < nk) {
            stage(kc + 1, buf ^ 1);
            asm volatile("cp.async.wait_group 1;" ::: "memory");
        } else {
            asm volatile("cp.async.wait_group 0;" ::: "memory");
        }
        __syncthreads();   // halo[buf] ready; prior MMAs (V readers) done

        // input transform: thread -> (tile, ic)
        {
            int tile = tid >> 4, ic = tid & 15;
            int hbase = (buf * 2) * HALO_HALVES
                + (((tile >> 2) * 2) * 10 + (tile & 3) * 2) * 24 + ic;
            float dd[4][4];
#pragma unroll
            for (int r = 0; r < 4; r++)
#pragma unroll
                for (int c = 0; c < 4; c++) {
                    int off = hbase + (r * 10 + c) * 24;
                    dd[r][c] = __half2float(dsm[off]) + __half2float(dsm[off + HALO_HALVES]);
                }
            float w4[4][4];
#pragma unroll
            for (int c = 0; c < 4; c++) {
                w4[0][c] = dd[0][c] - dd[2][c];
                w4[1][c] = dd[1][c] + dd[2][c];
                w4[2][c] = dd[2][c] - dd[1][c];
                w4[3][c] = dd[1][c] - dd[3][c];
            }
#pragma unroll
            for (int i = 0; i < 4; i++) {
                float v4[4];
                v4[0] = w4[i][0] - w4[i][2];
                v4[1] = w4[i][1] + w4[i][2];
                v4[2] = w4[i][2] - w4[i][1];
                v4[3] = w4[i][1] - w4[i][3];
#pragma unroll
                for (int j = 0; j < 4; j++) {
                    int pos = i * 4 + j;
                    __half vh = __float2half(v4[j]);
                    __half vl = __float2half(v4[j] - __half2float(vh));
                    int voff = V_OFF + ((pos * 2) * 16 + tile) * 24 + ic;
                    dsm[voff] = vh;
                    dsm[voff + V_PL] = vl;
                }
            }
        }
        __syncthreads();   // V ready

        // GEMMs: warp handles 2 positions
#pragma unroll
        for (int pp = 0; pp < 2; pp++) {
            int pos = wid * 2 + pp;
            uint32_t va = s32 + (uint32_t)(V_OFF + ((pos * 2) * 16 + (lane & 15)) * 24
                                           + ((lane >> 4) << 3)) * 2;
            uint32_t afh[4], afl[4];
            ldm_x4(va, afh);
            ldm_x4(va + V_PL * 2, afl);
#pragma unroll
            for (int p = 0; p < 4; p++) {
                long t = ((long)(pos * co16 + (oc0 >> 4) + p)) * ci16 + kc;
                uint4 vh = ufh4[t * 32 + lane];
                uint4 vl = ufl4[t * 32 + lane];
                mma16816(d[pp][2 * p],     afh, vh.x, vh.y);
                mma16816(d[pp][2 * p + 1], afh, vh.z, vh.w);
                mma16816(d[pp][2 * p],     afh, vl.x, vl.y);
                mma16816(d[pp][2 * p + 1], afh, vl.z, vl.w);
                mma16816(d[pp][2 * p],     afl, vh.x, vh.y);
                mma16816(d[pp][2 * p + 1], afl, vh.z, vh.w);
            }
        }
    }

    // epilogue: accumulators -> smem M, output transform, store
    __syncthreads();
    float* M = (float*)dsm;
#pragma unroll
    for (int pp = 0; pp < 2; pp++) {
        int pos = wid * 2 + pp;
#pragma unroll
        for (int p = 0; p < 4; p++)
#pragma unroll
            for (int q = 0; q < 2; q++)
#pragma unroll
                for (int e = 0; e < 4; e++) {
                    int tile = (lane >> 2) + (e >> 1) * 8;
                    int ocl = p * 16 + q * 8 + (lane & 3) * 2 + (e & 1);
                    M[pos * 1025 + tile * 64 + ocl] = d[pp][2 * p + q][e];
                }
    }
    __syncthreads();

#pragma unroll
    for (int it = 0; it < 2; it++) {
        int idx = tid + it * 256;
        int tile = idx >> 5;
        int oc2 = (idx & 31) * 2;
        float m0[4][4], m1[4][4];
#pragma unroll
        for (int i = 0; i < 4; i++)
#pragma unroll
            for (int j = 0; j < 4; j++) {
                int mo = (i * 4 + j) * 1025 + tile * 64 + oc2;
                m0[i][j] = M[mo];
                m1[i][j] = M[mo + 1];
            }
        float z0[2][4], z1[2][4];
#pragma unroll
        for (int j = 0; j < 4; j++) {
            z0[0][j] = m0[0][j] + m0[1][j] + m0[2][j];
            z0[1][j] = m0[1][j] - m0[2][j] - m0[3][j];
            z1[0][j] = m1[0][j] + m1[1][j] + m1[2][j];
            z1[1][j] = m1[1][j] - m1[2][j] - m1[3][j];
        }
        float y0[2][2], y1[2][2];
#pragma unroll
        for (int i = 0; i < 2; i++) {
            y0[i][0] = z0[i][0] + z0[i][1] + z0[i][2];
            y0[i][1] = z0[i][1] - z0[i][2] - z0[i][3];
            y1[i][0] = z1[i][0] + z1[i][1] + z1[i][2];
            y1[i][1] = z1[i][1] - z1[i][2] - z1[i][3];
        }
        float b0 = bias[oc0 + oc2], b1 = bias[oc0 + oc2 + 1];
#pragma unroll
        for (int dy = 0; dy < 2; dy++)
#pragma unroll
            for (int dx = 0; dx < 2; dx++) {
                int gy = ry0 + (tile >> 2) * 2 + dy;
                int gx = rx0 + (tile & 3) * 2 + dx;
                float v0 = y0[dy][dx] + b0;
                float v1 = y1[dy][dx] + b1;
                v0 = v0 > 0.f ? v0 : 0.f;
                v1 = v1 > 0.f ? v1 : 0.f;
                __half h0 = __float2half(v0);
                __half h1 = __float2half(v1);
                __half l0 = __float2half(v0 - __half2float(h0));
                __half l1 = __float2half(v1 - __half2float(h1));
                long oadr = ((long)(b * H + gy) * W + gx) * outStride + oc0 + oc2;
                *(__half2*)(outh + oadr) = __halves2half2(h0, h1);
                *(__half2*)(outl + oadr) = __halves2half2(l0, l1);
            }
    }
}

// ---------------------------------------------------------------------------
// 2x2 maxpool on NHWC hi/lo planes
// ---------------------------------------------------------------------------
__global__ void maxpool_hl_kernel(const __half* __restrict__ ih, const __half* __restrict__ il,
                                  __half* __restrict__ oh, __half* __restrict__ ol,
                                  int C, int Hi, int Wi, int nb) {
    int Ho = Hi >> 1, Wo = Wi >> 1;
    int C2 = C >> 1;
    long total = (long)nb * Ho * Wo * C2;
    for (long i = blockIdx.x * (long)blockDim.x + threadIdx.x; i < total;
         i += (long)gridDim.x * blockDim.x) {
        int c2 = (int)(i % C2);
        long p = i / C2;
        int x = (int)(p % Wo);
        long t = p / Wo;
        int y = (int)(t % Ho);
        int b = (int)(t / Ho);
        float m0 = -1e30f, m1 = -1e30f;
#pragma unroll
        for (int dy = 0; dy < 2; dy++)
#pragma unroll
            for (int dx = 0; dx < 2; dx++) {
                long base = ((long)(b * Hi + 2 * y + dy) * Wi + 2 * x + dx) * C + c2 * 2;
                float2 h = __half22float2(*(const __half2*)(ih + base));
                float2 l = __half22float2(*(const __half2*)(il + base));
                m0 = fmaxf(m0, h.x + l.x);
                m1 = fmaxf(m1, h.y + l.y);
            }
        long obase = ((long)(b * Ho + y) * Wo + x) * C + c2 * 2;
        __half h0 = __float2half(m0), h1 = __float2half(m1);
        *(__half2*)(oh + obase) = __halves2half2(h0, h1);
        *(__half2*)(ol + obase) = __halves2half2(__float2half(m0 - __half2float(h0)),
                                                 __float2half(m1 - __half2float(h1)));
    }
}

// ---------------------------------------------------------------------------
// Row norms (hi+lo), warp per 768-channel row
// ---------------------------------------------------------------------------
__global__ void norms_nhwc_kernel(const __half* __restrict__ fh, const __half* __restrict__ fl,
                                  float* __restrict__ rnorm) {
    int row = (blockIdx.x * blockDim.x + threadIdx.x) >> 5;
    int lane = threadIdx.x & 31;
    if (row >= NBATCH * FEAT_N) return;
    const __half2* ph = (const __half2*)(fh + (long)row * FEAT_C);
    const __half2* pl = (const __half2*)(fl + (long)row * FEAT_C);
    float s = 0.f;
#pragma unroll
    for (int j = 0; j < 12; j++) {
        int k = j * 32 + lane;
        float2 h = __half22float2(ph[k]);
        float2 l = __half22float2(pl[k]);
        float v0 = h.x + l.x, v1 = h.y + l.y;
        s = fmaf(v0, v0, fmaf(v1, v1, s));
    }
#pragma unroll
    for (int off = 16; off > 0; off >>= 1) s += __shfl_xor_sync(0xFFFFFFFF, s, off);
    if (lane == 0) rnorm[row] = 1.f / (sqrtf(s) + EPS);
}

// ---------------------------------------------------------------------------
// Normalize: hi/lo -> fp32 + fp16
// ---------------------------------------------------------------------------
__global__ void normalize_kernel(const __half* __restrict__ fh, const __half* __restrict__ fl,
                                 const float* __restrict__ rnorm,
                                 float* __restrict__ xn, __half* __restrict__ xh) {
    long total = (long)NBATCH * FEAT_N * (FEAT_C / 2);
    for (long i = blockIdx.x * (long)blockDim.x + threadIdx.x; i < total;
         i += (long)gridDim.x * blockDim.x) {
        long r = i / (FEAT_C / 2);
        float rn = rnorm[r];
        float2 h = __half22float2(*(const __half2*)(fh + i * 2));
        float2 l = __half22float2(*(const __half2*)(fl + i * 2));
        float v0 = (h.x + l.x) * rn;
        float v1 = (h.y + l.y) * rn;
        *(float2*)(xn + i * 2) = make_float2(v0, v1);
        *(__half2*)(xh + i * 2) = __halves2half2(__float2half(v0), __float2half(v1));
    }
}

// ---------------------------------------------------------------------------
// HMMA candidate search (verified)
// ---------------------------------------------------------------------------
__device__ __forceinline__ void merge_top2(float& a1, int& ai1, float& a2, int& ai2,
                                           float b1, int bi1, float b2, int bi2) {
    if (b1 > a1) {
        float tv = a1; int ti = ai1;
        a1 = b1; ai1 = bi1;
        b1 = tv; bi1 = ti;
        if (b2 > a2) { a2 = b2; ai2 = bi2; }
    }
    if (b1 > a2) { a2 = b1; ai2 = bi1; }
}

#define MM_PAD 40

__global__ __launch_bounds__(256)
void maxdot_mma_kernel(const __half* __restrict__ xh, const __half* __restrict__ sh,
                       int2* __restrict__ cand) {
    __shared__ __half sA[128][MM_PAD];
    __shared__ __half sB[128][MM_PAD];
    __shared__ float sVal[128][4];
    __shared__ int   sIdx[128][4];

    int tid = threadIdx.x;
    int lane = tid & 31;
    int wid = tid >> 5;
    int wn = wid & 3;
    int wm = wid >> 2;
    int b = blockIdx.y;
    int n0 = blockIdx.x * 128;

    float t1[4], t2[4];
    int i1[4], i2[4];
#pragma unroll
    for (int s = 0; s < 4; s++) { t1[s] = -1e30f; t2[s] = -1e30f; i1[s] = 0; i2[s] = 0; }

    int ldrow = tid >> 1;
    int ldseg = tid & 1;
    const __half* xrow = xh + ((long)(b * FEAT_N + n0 + ldrow)) * FEAT_C + ldseg * 16;

    int a_row = (lane & 15);
    int a_col8 = (lane >> 4) * 8;
    int b_row = (lane & 7) + ((lane >> 4) * 8);
    int b_col8 = ((lane >> 3) & 1) * 8;

    for (int mt = 0; mt < 32; mt++) {
        float d[2][8][4];
#pragma unroll
        for (int mf = 0; mf < 2; mf++)
#pragma unroll
            for (int nf = 0; nf < 8; nf++)
#pragma unroll
                for (int e = 0; e < 4; e++) d[mf][nf][e] = 0.f;

        const __half* srow = sh + ((long)(b * FEAT_N + mt * 128 + ldrow)) * FEAT_C + ldseg * 16;

        for (int kc = 0; kc < 24; kc++) {
            const uint4* xp = (const uint4*)(xrow + kc * 32);
            const uint4* spp = (const uint4*)(srow + kc * 32);
            uint4 va0 = xp[0], va1 = xp[1];
            uint4 vb0 = spp[0], vb1 = spp[1];
            *(uint4*)&sA[ldrow][ldseg * 16] = va0;
            *(uint4*)&sA[ldrow][ldseg * 16 + 8] = va1;
            *(uint4*)&sB[ldrow][ldseg * 16] = vb0;
            *(uint4*)&sB[ldrow][ldseg * 16 + 8] = vb1;
            __syncthreads();

#pragma unroll
            for (int ks = 0; ks < 2; ks++) {
                uint32_t bf[4][4];
#pragma unroll
                for (int p = 0; p < 4; p++) {
                    uint32_t ad = smem_addr32(&sB[wm * 64 + p * 16 + b_row][ks * 16 + b_col8]);
                    ldm_x4(ad, bf[p]);
                }
#pragma unroll
                for (int mf = 0; mf < 2; mf++) {
                    uint32_t af[4];
                    uint32_t ad = smem_addr32(&sA[wn * 32 + mf * 16 + a_row][ks * 16 + a_col8]);
                    ldm_x4(ad, af);
#pragma unroll
                    for (int p = 0; p < 4; p++) {
                        mma16816(d[mf][2 * p],     af, bf[p][0], bf[p][1]);
                        mma16816(d[mf][2 * p + 1], af, bf[p][2], bf[p][3]);
                    }
                }
            }
            __syncthreads();
        }

#pragma unroll
        for (int mf = 0; mf < 2; mf++)
#pragma unroll
            for (int nf = 0; nf < 8; nf++) {
                int colb = mt * 128 + wm * 64 + nf * 8 + (lane & 3) * 2;
#pragma unroll
                for (int e = 0; e < 4; e++) {
                    int s = mf * 2 + (e >> 1);
                    float v = d[mf][nf][e];
                    int m = colb + (e & 1);
                    if (v > t1[s]) { t2[s] = t1[s]; i2[s] = i1[s]; t1[s] = v; i1[s] = m; }
                    else if (v > t2[s]) { t2[s] = v; i2[s] = m; }
                }
            }
    }

#pragma unroll
    for (int off = 1; off <= 2; off <<= 1) {
#pragma unroll
        for (int s = 0; s < 4; s++) {
            float o1 = __shfl_xor_sync(0xFFFFFFFF, t1[s], off);
            float o2 = __shfl_xor_sync(0xFFFFFFFF, t2[s], off);
            int oi1 = __shfl_xor_sync(0xFFFFFFFF, i1[s], off);
            int oi2 = __shfl_xor_sync(0xFFFFFFFF, i2[s], off);
            merge_top2(t1[s], i1[s], t2[s], i2[s], o1, oi1, o2, oi2);
        }
    }

    if ((lane & 3) == 0) {
#pragma unroll
        for (int s = 0; s < 4; s++) {
            int mf = s >> 1;
            int hi = s & 1;
            int row = wn * 32 + mf * 16 + (lane >> 2) + hi * 8;
            sVal[row][wm * 2 + 0] = t1[s];
            sVal[row][wm * 2 + 1] = t2[s];
            sIdx[row][wm * 2 + 0] = i1[s];
            sIdx[row][wm * 2 + 1] = i2[s];
        }
    }
    __syncthreads();

    if (tid < 128) {
        float a1 = sVal[tid][0], a2 = sVal[tid][1];
        int ai1 = sIdx[tid][0], ai2 = sIdx[tid][1];
        merge_top2(a1, ai1, a2, ai2, sVal[tid][2], sIdx[tid][2], sVal[tid][3], sIdx[tid][3]);
        cand[b * FEAT_N + n0 + tid] = make_int2(ai1, ai2);
    }
}

// ---------------------------------------------------------------------------
// Exact fp32 rescore + final reduction
// ---------------------------------------------------------------------------
__global__ void rescore_kernel(const float* __restrict__ xn, const float* __restrict__ sn,
                               const int2* __restrict__ cand, float* __restrict__ rowmax) {
    int gwarp = (blockIdx.x * blockDim.x + threadIdx.x) >> 5;
    int lane = threadIdx.x & 31;
    if (gwarp >= BATCH * FEAT_N) return;
    int b = gwarp >> 12;
    int2 c = cand[gwarp];
    const float4* xr = (const float4*)(xn + (long)gwarp * FEAT_C);
    const float4* s1 = (const float4*)(sn + ((long)(b << 12) + c.x) * FEAT_C);
    const float4* s2 = (const float4*)(sn + ((long)(b << 12) + c.y) * FEAT_C);
    float d1 = 0.f, d2 = 0.f;
#pragma unroll
    for (int i = 0; i < 6; i++) {
        int k = i * 32 + lane;
        float4 xv = xr[k], a = s1[k], bb = s2[k];
        d1 += xv.x * a.x + xv.y * a.y + xv.z * a.z + xv.w * a.w;
        d2 += xv.x * bb.x + xv.y * bb.y + xv.z * bb.z + xv.w * bb.w;
    }
#pragma unroll
    for (int off = 16; off > 0; off >>= 1) {
        d1 += __shfl_xor_sync(0xFFFFFFFF, d1, off);
        d2 += __shfl_xor_sync(0xFFFFFFFF, d2, off);
    }
    if (lane == 0) rowmax[gwarp] = fmaxf(d1, d2);
}

__global__ void loss_kernel(const float* __restrict__ rowmax, float* __restrict__ out) {
    __shared__ float sred[256];
    float s = 0.f;
    for (int i = threadIdx.x; i < BATCH * FEAT_N; i += 256)
        s += 1.0f - rowmax[i];
    sred[threadIdx.x] = s;
    __syncthreads();
    for (int k = 128; k > 0; k >>= 1) {
        if (threadIdx.x < k) sred[threadIdx.x] += sred[threadIdx.x + k];
        __syncthreads();
    }
    if (threadIdx.x == 0) out[0] = sred[0] / (float)(BATCH * FEAT_N);
}

// ---------------------------------------------------------------------------
// Host orchestration
// ---------------------------------------------------------------------------
static void launch_wino(const __half* ih, const __half* il,
                        const __half* uh, const __half* ul, const float* bias,
                        __half* oh, __half* ol,
                        int Cin, int Cout, int H, int W, int inStride, int outStride) {
    dim3 grid(W / 8, H / 8, NBATCH * (Cout / 64));
    conv_wino_kernel<<<grid, 256, WINO_SMEM>>>(ih, il, uh, ul, bias, oh, ol,
                                               Cin, Cout, H, W, inStride, outStride);
}

extern "C" void kernel_launch(void* const* d_in, const int* in_sizes, int n_in,
                              void* d_out, int out_size) {
    const float* outputs = (const float*)d_in[0];
    const float* styles  = (const float*)d_in[1];
    const float* w[7];
    const float* bi[7];
    for (int i = 0; i < 7; i++) {
        w[i]  = (const float*)d_in[2 + 2 * i];
        bi[i] = (const float*)d_in[3 + 2 * i];
    }

    __half *Ah, *Al, *Bh, *Bl, *fh, *fl, *uh, *ul, *xhh;
    float *xn, *rnorm, *rowmax;
    int2* cand;
    cudaGetSymbolAddress((void**)&Ah, g_Ah);
    cudaGetSymbolAddress((void**)&Al, g_Al);
    cudaGetSymbolAddress((void**)&Bh, g_Bh);
    cudaGetSymbolAddress((void**)&Bl, g_Bl);
    cudaGetSymbolAddress((void**)&fh, g_feath);
    cudaGetSymbolAddress((void**)&fl, g_featl);
    cudaGetSymbolAddress((void**)&uh, g_uh);
    cudaGetSymbolAddress((void**)&ul, g_ul);
    cudaGetSymbolAddress((void**)&xn, g_xn);
    cudaGetSymbolAddress((void**)&xhh, g_xh);
    cudaGetSymbolAddress((void**)&rnorm, g_rnorm);
    cudaGetSymbolAddress((void**)&rowmax, g_rowmax);
    cudaGetSymbolAddress((void**)&cand, g_cand);

    cudaFuncSetAttribute(conv_wino_kernel, cudaFuncAttributeMaxDynamicSharedMemorySize,
                         WINO_SMEM);

    // Winograd weight transform + fragment prep
    uprep_kernel<<<16, 256>>>(w[1], uh + U12_OFF, ul + U12_OFF, 64, 64);
    uprep_kernel<<<32, 256>>>(w[2], uh + U21_OFF, ul + U21_OFF, 128, 64);
    uprep_kernel<<<64, 256>>>(w[3], uh + U22_OFF, ul + U22_OFF, 128, 128);
    uprep_kernel<<<128, 256>>>(w[4], uh + U31_OFF, ul + U31_OFF, 256, 128);
    uprep_kernel<<<256, 256>>>(w[5], uh + U32_OFF, ul + U32_OFF, 256, 256);
    uprep_kernel<<<256, 256>>>(w[6], uh + U33_OFF, ul + U33_OFF, 256, 256);

    // fused batch-8 feature extraction
    conv1_kernel<<<NBATCH * 65536 / 256, 256>>>(outputs, styles, w[0], bi[0], Ah, Al);
    launch_wino(Ah, Al, uh + U12_OFF, ul + U12_OFF, bi[1], Bh, Bl,
                64, 64, 256, 256, 64, 64);
    maxpool_hl_kernel<<<4096, 256>>>(Bh, Bl, Ah, Al, 64, 256, 256, NBATCH);
    launch_wino(Ah, Al, uh + U21_OFF, ul + U21_OFF, bi[2], Bh, Bl,
                64, 128, 128, 128, 64, 128);
    launch_wino(Bh, Bl, uh + U22_OFF, ul + U22_OFF, bi[3], Ah, Al,
                128, 128, 128, 128, 128, 128);
    maxpool_hl_kernel<<<2048, 256>>>(Ah, Al, Bh, Bl, 128, 128, 128, NBATCH);
    launch_wino(Bh, Bl, uh + U31_OFF, ul + U31_OFF, bi[4], fh, fl,
                128, 256, 64, 64, 128, 768);
    launch_wino(fh, fl, uh + U32_OFF, ul + U32_OFF, bi[5], fh + 256, fl + 256,
                256, 256, 64, 64, 768, 768);
    launch_wino(fh + 256, fl + 256, uh + U33_OFF, ul + U33_OFF, bi[6],
                fh + 512, fl + 512, 256, 256, 64, 64, 768, 768);

    norms_nhwc_kernel<<<(NBATCH * FEAT_N * 32 + 255) / 256, 256>>>(fh, fl, rnorm);
    normalize_kernel<<<4096, 256>>>(fh, fl, rnorm, xn, xhh);

    const long soff = (long)BATCH * FEAT_N * FEAT_C;
    dim3 mg(FEAT_N / 128, BATCH);
    maxdot_mma_kernel<<<mg, 256>>>(xhh, xhh + soff, cand);
    rescore_kernel<<<(BATCH * FEAT_N) / 8, 256>>>(xn, xn + soff, cand, rowmax);
    loss_kernel<<<1, 256>>>(rowmax, (float*)d_out);
}

// round 12
// speedup vs baseline: 1.6309x; 1.6309x over previous
#include <cuda_runtime.h>
#include <cuda_fp16.h>
#include <math.h>
#include <stdint.h>

// ---------------------------------------------------------------------------
// Problem constants
// ---------------------------------------------------------------------------
#define BATCH 4
#define NBATCH 8            // outputs(0-3) + styles(4-7) fused
#define FEAT_C 768
#define FEAT_N 4096
#define EPS 1e-8f

// ---------------------------------------------------------------------------
// Device scratch (no allocations allowed). NHWC hi/lo fp16 activation planes.
// ---------------------------------------------------------------------------
#define ACT_ELEMS (NBATCH * 256 * 256 * 64)
__device__ __align__(128) __half g_Ah[ACT_ELEMS];
__device__ __align__(128) __half g_Al[ACT_ELEMS];
__device__ __align__(128) __half g_Bh[ACT_ELEMS];
__device__ __align__(128) __half g_Bl[ACT_ELEMS];
__device__ __align__(128) __half g_feath[NBATCH * FEAT_N * FEAT_C];
__device__ __align__(128) __half g_featl[NBATCH * FEAT_N * FEAT_C];
#define WPOOL_ELEMS 1732608
__device__ __align__(128) __half g_wh[WPOOL_ELEMS];
__device__ __align__(128) __half g_wl[WPOOL_ELEMS];
__device__ __align__(128) float  g_xn[NBATCH * FEAT_N * FEAT_C];
__device__ __align__(128) __half g_xh[NBATCH * FEAT_N * FEAT_C];
__device__ float g_rnorm[NBATCH * FEAT_N];
__device__ float g_rowmax[BATCH * FEAT_N];
__device__ int2  g_cand[BATCH * FEAT_N];

// Weight pool offsets (halves; fragment-permuted within each layer block)
#define W12_OFF 0         // 64x64
#define W21_OFF 36864     // 128x64
#define W22_OFF 110592    // 128x128
#define W31_OFF 258048    // 256x128
#define W32_OFF 552960    // 256x256
#define W33_OFF 1142784   // 256x256

// ---------------------------------------------------------------------------
// mma.sync helpers (verified)
// ---------------------------------------------------------------------------
__device__ __forceinline__ uint32_t smem_addr32(const void* p) {
    return (uint32_t)__cvta_generic_to_shared(p);
}
__device__ __forceinline__ void ldm_x4(uint32_t addr, uint32_t r[4]) {
    asm volatile("ldmatrix.sync.aligned.m8n8.x4.shared.b16 {%0,%1,%2,%3}, [%4];"
                 : "=r"(r[0]), "=r"(r[1]), "=r"(r[2]), "=r"(r[3]) : "r"(addr));
}
__device__ __forceinline__ void mma16816(float d[4], const uint32_t a[4],
                                         uint32_t b0, uint32_t b1) {
    asm volatile(
        "mma.sync.aligned.m16n8k16.row.col.f32.f16.f16.f32 "
        "{%0,%1,%2,%3}, {%4,%5,%6,%7}, {%8,%9}, {%0,%1,%2,%3};"
        : "+f"(d[0]), "+f"(d[1]), "+f"(d[2]), "+f"(d[3])
        : "r"(a[0]), "r"(a[1]), "r"(a[2]), "r"(a[3]), "r"(b0), "r"(b1));
}
__device__ __forceinline__ void cp_async16(uint32_t saddr, const void* gaddr, int srcsz) {
    asm volatile("cp.async.ca.shared.global [%0], [%1], 16, %2;"
                 :: "r"(saddr), "l"(gaddr), "r"(srcsz));
}

// ---------------------------------------------------------------------------
// Weight prep: fp32 OIHW -> hi/lo fp16 fragment-ordered tiles
// tile = (tap*(Co/16) + oc16)*(Ci/16) + kc ; 128 u32 per tile = [lane][reg j]
// reg j, lane l -> oc = oc16*16 + (j>>1)*8 + l/4 ; ic = kc*16 + (j&1)*8 + 2*(l%4)
// ---------------------------------------------------------------------------
__global__ void wprep_frag_kernel(const float* __restrict__ w, __half* __restrict__ wh,
                                  __half* __restrict__ wl, int Cout, int Cin) {
    uint32_t* whu = (uint32_t*)wh;
    uint32_t* wlu = (uint32_t*)wl;
    int ci16 = Cin >> 4, co16 = Cout >> 4;
    int total = 9 * co16 * ci16 * 128;
    for (int i = blockIdx.x * blockDim.x + threadIdx.x; i < total;
         i += gridDim.x * blockDim.x) {
        int tile = i >> 7;
        int r = i & 127;
        int lane = r >> 2, j = r & 3;
        int tap = tile / (co16 * ci16);
        int rem = tile - tap * co16 * ci16;
        int o16 = rem / ci16;
        int kc = rem - o16 * ci16;
        int oc = o16 * 16 + ((j >> 1) << 3) + (lane >> 2);
        int ic = kc * 16 + ((j & 1) << 3) + ((lane & 3) << 1);
        float v0 = w[((long)oc * Cin + ic) * 9 + tap];
        float v1 = w[((long)oc * Cin + ic + 1) * 9 + tap];
        __half h0 = __float2half(v0), h1 = __float2half(v1);
        __half l0 = __float2half(v0 - __half2float(h0));
        __half l1 = __float2half(v1 - __half2float(h1));
        __half2 hh = __halves2half2(h0, h1);
        __half2 ll = __halves2half2(l0, l1);
        whu[i] = *(uint32_t*)&hh;
        wlu[i] = *(uint32_t*)&ll;
    }
}

// ---------------------------------------------------------------------------
// conv1_1: fused normalize + 3->64 conv + bias + relu (batch 8, two sources)
// ---------------------------------------------------------------------------
__global__ __launch_bounds__(256)
void conv1_kernel(const float* __restrict__ imgA, const float* __restrict__ imgB,
                  const float* __restrict__ w, const float* __restrict__ bias,
                  __half* __restrict__ oh, __half* __restrict__ ol) {
    __shared__ float sw[64 * 27];
    __shared__ float sb[64];
    int tid = threadIdx.x;
    for (int i = tid; i < 64 * 27; i += 256) sw[i] = w[i];
    if (tid < 64) sb[tid] = bias[tid];
    __syncthreads();

    const float mean[3] = {0.485f, 0.456f, 0.406f};
    const float istd[3] = {1.f / 0.229f, 1.f / 0.224f, 1.f / 0.225f};

    int gid = blockIdx.x * 256 + tid;
    int b = gid >> 16;
    int y = (gid >> 8) & 255;
    int x = gid & 255;
    const float* base = (b < 4) ? imgA : imgB;
    int bb = b & 3;

    float in[3][9];
#pragma unroll
    for (int c = 0; c < 3; c++) {
        const float* ip = base + (((long)bb * 3 + c) << 16);
#pragma unroll
        for (int dy = 0; dy < 3; dy++)
#pragma unroll
            for (int dx = 0; dx < 3; dx++) {
                int gy = y + dy - 1, gx = x + dx - 1;
                float v = 0.f;
                if (gy >= 0 && gy < 256 && gx >= 0 && gx < 256)
                    v = (ip[(gy << 8) + gx] - mean[c]) * istd[c];
                in[c][dy * 3 + dx] = v;
            }
    }

    long obase = (long)gid * 64;
#pragma unroll 4
    for (int oc = 0; oc < 64; oc++) {
        float acc = sb[oc];
        const float* wp = &sw[oc * 27];
#pragma unroll
        for (int c = 0; c < 3; c++)
#pragma unroll
            for (int k = 0; k < 9; k++)
                acc = fmaf(in[c][k], wp[c * 9 + k], acc);
        acc = acc > 0.f ? acc : 0.f;
        __half h = __float2half(acc);
        oh[obase + oc] = h;
        ol[obase + oc] = __float2half(acc - __half2float(h));
    }
}

// ---------------------------------------------------------------------------
// Tensor-core 3x3 conv: 9 shifted GEMMs, split-fp16 (hh+hl+lh).
// Weight fragments: global loads, software-pipelined one tap ahead (register
// double buffer). A: cp.async double buffer, ONE barrier per k-chunk.
// Block 256 thr; tile 8x16 px x 64 oc; k-chunk 16 ic.
// ---------------------------------------------------------------------------
#define HALO_W 18
#define HALO_PX 180
#define SPAD 24
#define APLANE (HALO_PX * SPAD)     // 4320 halves per plane

__global__ __launch_bounds__(256)
void conv_mma_kernel(const __half* __restrict__ inh, const __half* __restrict__ inl,
                     const __half* __restrict__ wfh, const __half* __restrict__ wfl,
                     const float* __restrict__ bias,
                     __half* __restrict__ outh, __half* __restrict__ outl,
                     int Cin, int Cout, int H, int W,
                     int inStride, int outStride) {
    __shared__ __align__(16) __half smem[4 * APLANE];   // [buf][plane][180][24]
    uint32_t sb32 = smem_addr32(smem);

    int tid = threadIdx.x;
    int lane = tid & 31;
    int wid = tid >> 5;
    int wn = wid & 3;      // pixel row group
    int wm = wid >> 2;     // oc half (32 each)

    int ocb = Cout >> 6;
    int b = blockIdx.z / ocb;
    int oc0 = (blockIdx.z % ocb) << 6;
    int py0 = blockIdx.y * 8 - 1;
    int px0 = blockIdx.x * 16 - 1;

    int a_row = lane & 15;
    int a_col8 = (lane >> 4) * 8;
    int nk = Cin >> 4;
    int co16 = Cout >> 4, ci16 = Cin >> 4;
    const uint4* wfh4 = (const uint4*)wfh;
    const uint4* wfl4 = (const uint4*)wfl;

    float d[2][4][4];
#pragma unroll
    for (int i = 0; i < 2; i++)
#pragma unroll
        for (int j = 0; j < 4; j++)
#pragma unroll
            for (int e = 0; e < 4; e++) d[i][j][e] = 0.f;

    auto stage = [&](int kc, int buf) {
        int icc = kc << 4;
        for (int u = tid; u < 720; u += 256) {
            int plane = u >= 360;
            int idx = u - (plane ? 360 : 0);
            int px = idx >> 1, seg = idx & 1;
            int r = px / HALO_W, c = px - r * HALO_W;
            int gy = py0 + r, gx = px0 + c;
            int valid = (gy >= 0 && gy < H && gx >= 0 && gx < W) ? 16 : 0;
            int gyc = gy < 0 ? 0 : (gy >= H ? H - 1 : gy);
            int gxc = gx < 0 ? 0 : (gx >= W ? W - 1 : gx);
            const __half* gp = (plane ? inl : inh)
                + ((long)(b * H + gyc) * W + gxc) * inStride + icc + seg * 8;
            uint32_t sa = sb32 + ((buf * 2 + plane) * APLANE + px * SPAD + seg * 8) * 2;
            cp_async16(sa, gp, valid);
        }
        asm volatile("cp.async.commit_group;" ::: "memory");
    };

    stage(0, 0);
    int tb = (oc0 >> 4) + wm * 2;

    for (int kc = 0; kc < nk; kc++) {
        int buf = kc & 1;
        asm volatile("cp.async.wait_group 0;" ::: "memory");
        __syncthreads();
        if (kc + 1 < nk) stage(kc + 1, buf ^ 1);

        // preload tap 0 weight fragments
        uint4 pvh[2][2], pvl[2][2];
#pragma unroll
        for (int p = 0; p < 2; p++) {
            long t = ((long)(tb + p)) * ci16 + kc;
            pvh[0][p] = wfh4[t * 32 + lane];
            pvl[0][p] = wfl4[t * 32 + lane];
        }

#pragma unroll
        for (int tap = 0; tap < 9; tap++) {
            int cur = tap & 1, nxt = cur ^ 1;
            if (tap < 8) {
                // prefetch next tap's fragments (overlaps this tap's MMAs)
#pragma unroll
                for (int p = 0; p < 2; p++) {
                    long t = ((long)((tap + 1) * co16 + tb + p)) * ci16 + kc;
                    pvh[nxt][p] = wfh4[t * 32 + lane];
                    pvl[nxt][p] = wfl4[t * 32 + lane];
                }
            }
            int ky = tap / 3, kx = tap - ky * 3;
#pragma unroll
            for (int ar = 0; ar < 2; ar++) {
                int pr = wn * 2 + ar;
                uint32_t offA = sb32
                    + ((buf * 2) * APLANE + ((pr + ky) * HALO_W + kx + a_row) * SPAD + a_col8) * 2;
                uint32_t afh[4], afl[4];
                ldm_x4(offA, afh);
                ldm_x4(offA + APLANE * 2, afl);
#pragma unroll
                for (int p = 0; p < 2; p++) {
                    mma16816(d[ar][2 * p],     afh, pvh[cur][p].x, pvh[cur][p].y);
                    mma16816(d[ar][2 * p + 1], afh, pvh[cur][p].z, pvh[cur][p].w);
                    mma16816(d[ar][2 * p],     afh, pvl[cur][p].x, pvl[cur][p].y);
                    mma16816(d[ar][2 * p + 1], afh, pvl[cur][p].z, pvl[cur][p].w);
                    mma16816(d[ar][2 * p],     afl, pvh[cur][p].x, pvh[cur][p].y);
                    mma16816(d[ar][2 * p + 1], afl, pvh[cur][p].z, pvh[cur][p].w);
                }
            }
        }
    }

    // epilogue: bias + relu + hi/lo split (registers -> global, no smem)
    int obase_oc = oc0 + wm * 32 + (lane & 3) * 2;
    float2 bv[4];
#pragma unroll
    for (int nf = 0; nf < 4; nf++)
        bv[nf] = *(const float2*)(bias + obase_oc + nf * 8);

#pragma unroll
    for (int ar = 0; ar < 2; ar++) {
        int gy = blockIdx.y * 8 + wn * 2 + ar;
#pragma unroll
        for (int eh = 0; eh < 2; eh++) {
            int gx = blockIdx.x * 16 + (lane >> 2) + eh * 8;
            long pbase = ((long)(b * H + gy) * W + gx) * outStride;
#pragma unroll
            for (int nf = 0; nf < 4; nf++) {
                float v0 = d[ar][nf][eh * 2 + 0] + bv[nf].x;
                float v1 = d[ar][nf][eh * 2 + 1] + bv[nf].y;
                v0 = v0 > 0.f ? v0 : 0.f;
                v1 = v1 > 0.f ? v1 : 0.f;
                __half h0 = __float2half(v0);
                __half h1 = __float2half(v1);
                __half l0 = __float2half(v0 - __half2float(h0));
                __half l1 = __float2half(v1 - __half2float(h1));
                long oadr = pbase + obase_oc + nf * 8;
                *(__half2*)(outh + oadr) = __halves2half2(h0, h1);
                *(__half2*)(outl + oadr) = __halves2half2(l0, l1);
            }
        }
    }
}

// ---------------------------------------------------------------------------
// 2x2 maxpool on NHWC hi/lo planes
// ---------------------------------------------------------------------------
__global__ void maxpool_hl_kernel(const __half* __restrict__ ih, const __half* __restrict__ il,
                                  __half* __restrict__ oh, __half* __restrict__ ol,
                                  int C, int Hi, int Wi, int nb) {
    int Ho = Hi >> 1, Wo = Wi >> 1;
    int C2 = C >> 1;
    long total = (long)nb * Ho * Wo * C2;
    for (long i = blockIdx.x * (long)blockDim.x + threadIdx.x; i < total;
         i += (long)gridDim.x * blockDim.x) {
        int c2 = (int)(i % C2);
        long p = i / C2;
        int x = (int)(p % Wo);
        long t = p / Wo;
        int y = (int)(t % Ho);
        int b = (int)(t / Ho);
        float m0 = -1e30f, m1 = -1e30f;
#pragma unroll
        for (int dy = 0; dy < 2; dy++)
#pragma unroll
            for (int dx = 0; dx < 2; dx++) {
                long base = ((long)(b * Hi + 2 * y + dy) * Wi + 2 * x + dx) * C + c2 * 2;
                float2 h = __half22float2(*(const __half2*)(ih + base));
                float2 l = __half22float2(*(const __half2*)(il + base));
                m0 = fmaxf(m0, h.x + l.x);
                m1 = fmaxf(m1, h.y + l.y);
            }
        long obase = ((long)(b * Ho + y) * Wo + x) * C + c2 * 2;
        __half h0 = __float2half(m0), h1 = __float2half(m1);
        *(__half2*)(oh + obase) = __halves2half2(h0, h1);
        *(__half2*)(ol + obase) = __halves2half2(__float2half(m0 - __half2float(h0)),
                                                 __float2half(m1 - __half2float(h1)));
    }
}

// ---------------------------------------------------------------------------
// Row norms (hi+lo), warp per 768-channel row
// ---------------------------------------------------------------------------
__global__ void norms_nhwc_kernel(const __half* __restrict__ fh, const __half* __restrict__ fl,
                                  float* __restrict__ rnorm) {
    int row = (blockIdx.x * blockDim.x + threadIdx.x) >> 5;
    int lane = threadIdx.x & 31;
    if (row >= NBATCH * FEAT_N) return;
    const __half2* ph = (const __half2*)(fh + (long)row * FEAT_C);
    const __half2* pl = (const __half2*)(fl + (long)row * FEAT_C);
    float s = 0.f;
#pragma unroll
    for (int j = 0; j < 12; j++) {
        int k = j * 32 + lane;
        float2 h = __half22float2(ph[k]);
        float2 l = __half22float2(pl[k]);
        float v0 = h.x + l.x, v1 = h.y + l.y;
        s = fmaf(v0, v0, fmaf(v1, v1, s));
    }
#pragma unroll
    for (int off = 16; off > 0; off >>= 1) s += __shfl_xor_sync(0xFFFFFFFF, s, off);
    if (lane == 0) rnorm[row] = 1.f / (sqrtf(s) + EPS);
}

// ---------------------------------------------------------------------------
// Normalize: hi/lo -> fp32 + fp16
// ---------------------------------------------------------------------------
__global__ void normalize_kernel(const __half* __restrict__ fh, const __half* __restrict__ fl,
                                 const float* __restrict__ rnorm,
                                 float* __restrict__ xn, __half* __restrict__ xh) {
    long total = (long)NBATCH * FEAT_N * (FEAT_C / 2);
    for (long i = blockIdx.x * (long)blockDim.x + threadIdx.x; i < total;
         i += (long)gridDim.x * blockDim.x) {
        long r = i / (FEAT_C / 2);
        float rn = rnorm[r];
        float2 h = __half22float2(*(const __half2*)(fh + i * 2));
        float2 l = __half22float2(*(const __half2*)(fl + i * 2));
        float v0 = (h.x + l.x) * rn;
        float v1 = (h.y + l.y) * rn;
        *(float2*)(xn + i * 2) = make_float2(v0, v1);
        *(__half2*)(xh + i * 2) = __halves2half2(__float2half(v0), __float2half(v1));
    }
}

// ---------------------------------------------------------------------------
// HMMA candidate search, cp.async double-buffered staging (1 barrier/chunk)
// ---------------------------------------------------------------------------
__device__ __forceinline__ void merge_top2(float& a1, int& ai1, float& a2, int& ai2,
                                           float b1, int bi1, float b2, int bi2) {
    if (b1 > a1) {
        float tv = a1; int ti = ai1;
        a1 = b1; ai1 = bi1;
        b1 = tv; bi1 = ti;
        if (b2 > a2) { a2 = b2; ai2 = bi2; }
    }
    if (b1 > a2) { a2 = b1; ai2 = bi1; }
}

#define MM_PAD 40

__global__ __launch_bounds__(256)
void maxdot_mma_kernel(const __half* __restrict__ xh, const __half* __restrict__ sfeat,
                       int2* __restrict__ cand) {
    __shared__ __align__(16) __half sA[2][128][MM_PAD];
    __shared__ __align__(16) __half sB[2][128][MM_PAD];
    __shared__ float sVal[128][4];
    __shared__ int   sIdx[128][4];

    int tid = threadIdx.x;
    int lane = tid & 31;
    int wid = tid >> 5;
    int wn = wid & 3;
    int wm = wid >> 2;
    int b = blockIdx.y;
    int n0 = blockIdx.x * 128;

    float t1[4], t2[4];
    int i1[4], i2[4];
#pragma unroll
    for (int s = 0; s < 4; s++) { t1[s] = -1e30f; t2[s] = -1e30f; i1[s] = 0; i2[s] = 0; }

    int ldrow = tid >> 1;
    int ldseg = tid & 1;
    const __half* xrow = xh + ((long)(b * FEAT_N + n0 + ldrow)) * FEAT_C + ldseg * 16;
    const __half* srowbase = sfeat + ((long)(b * FEAT_N + ldrow)) * FEAT_C + ldseg * 16;

    int a_row = (lane & 15);
    int a_col8 = (lane >> 4) * 8;
    int b_row = (lane & 7) + ((lane >> 4) * 8);
    int b_col8 = ((lane >> 3) & 1) * 8;

    auto stage2 = [&](int mt, int kc, int buf) {
        const __half* xp = xrow + kc * 32;
        uint32_t aa = smem_addr32(&sA[buf][ldrow][ldseg * 16]);
        cp_async16(aa, xp, 16);
        cp_async16(aa + 16, xp + 8, 16);
        const __half* sp = srowbase + (long)mt * 128 * FEAT_C + kc * 32;
        uint32_t ba = smem_addr32(&sB[buf][ldrow][ldseg * 16]);
        cp_async16(ba, sp, 16);
        cp_async16(ba + 16, sp + 8, 16);
        asm volatile("cp.async.commit_group;" ::: "memory");
    };

    stage2(0, 0, 0);

    for (int mt = 0; mt < 32; mt++) {
        float d[2][8][4];
#pragma unroll
        for (int mf = 0; mf < 2; mf++)
#pragma unroll
            for (int nf = 0; nf < 8; nf++)
#pragma unroll
                for (int e = 0; e < 4; e++) d[mf][nf][e] = 0.f;

        for (int kc = 0; kc < 24; kc++) {
            int it = mt * 24 + kc;
            int buf = it & 1;
            asm volatile("cp.async.wait_group 0;" ::: "memory");
            __syncthreads();
            int nit = it + 1;
            if (nit < 768) stage2(nit / 24, nit % 24, buf ^ 1);

#pragma unroll
            for (int ks = 0; ks < 2; ks++) {
                uint32_t bf[4][4];
#pragma unroll
                for (int p = 0; p < 4; p++) {
                    uint32_t ad = smem_addr32(&sB[buf][wm * 64 + p * 16 + b_row][ks * 16 + b_col8]);
                    ldm_x4(ad, bf[p]);
                }
#pragma unroll
                for (int mf = 0; mf < 2; mf++) {
                    uint32_t af[4];
                    uint32_t ad = smem_addr32(&sA[buf][wn * 32 + mf * 16 + a_row][ks * 16 + a_col8]);
                    ldm_x4(ad, af);
#pragma unroll
                    for (int p = 0; p < 4; p++) {
                        mma16816(d[mf][2 * p],     af, bf[p][0], bf[p][1]);
                        mma16816(d[mf][2 * p + 1], af, bf[p][2], bf[p][3]);
                    }
                }
            }
        }

#pragma unroll
        for (int mf = 0; mf < 2; mf++)
#pragma unroll
            for (int nf = 0; nf < 8; nf++) {
                int colb = mt * 128 + wm * 64 + nf * 8 + (lane & 3) * 2;
#pragma unroll
                for (int e = 0; e < 4; e++) {
                    int s = mf * 2 + (e >> 1);
                    float v = d[mf][nf][e];
                    int m = colb + (e & 1);
                    if (v > t1[s]) { t2[s] = t1[s]; i2[s] = i1[s]; t1[s] = v; i1[s] = m; }
                    else if (v > t2[s]) { t2[s] = v; i2[s] = m; }
                }
            }
    }

#pragma unroll
    for (int off = 1; off <= 2; off <<= 1) {
#pragma unroll
        for (int s = 0; s < 4; s++) {
            float o1 = __shfl_xor_sync(0xFFFFFFFF, t1[s], off);
            float o2 = __shfl_xor_sync(0xFFFFFFFF, t2[s], off);
            int oi1 = __shfl_xor_sync(0xFFFFFFFF, i1[s], off);
            int oi2 = __shfl_xor_sync(0xFFFFFFFF, i2[s], off);
            merge_top2(t1[s], i1[s], t2[s], i2[s], o1, oi1, o2, oi2);
        }
    }

    if ((lane & 3) == 0) {
#pragma unroll
        for (int s = 0; s < 4; s++) {
            int mf = s >> 1;
            int hi = s & 1;
            int row = wn * 32 + mf * 16 + (lane >> 2) + hi * 8;
            sVal[row][wm * 2 + 0] = t1[s];
            sVal[row][wm * 2 + 1] = t2[s];
            sIdx[row][wm * 2 + 0] = i1[s];
            sIdx[row][wm * 2 + 1] = i2[s];
        }
    }
    __syncthreads();

    if (tid < 128) {
        float a1 = sVal[tid][0], a2 = sVal[tid][1];
        int ai1 = sIdx[tid][0], ai2 = sIdx[tid][1];
        merge_top2(a1, ai1, a2, ai2, sVal[tid][2], sIdx[tid][2], sVal[tid][3], sIdx[tid][3]);
        cand[b * FEAT_N + n0 + tid] = make_int2(ai1, ai2);
    }
}

// ---------------------------------------------------------------------------
// Exact fp32 rescore + final reduction
// ---------------------------------------------------------------------------
__global__ void rescore_kernel(const float* __restrict__ xn, const float* __restrict__ sn,
                               const int2* __restrict__ cand, float* __restrict__ rowmax) {
    int gwarp = (blockIdx.x * blockDim.x + threadIdx.x) >> 5;
    int lane = threadIdx.x & 31;
    if (gwarp >= BATCH * FEAT_N) return;
    int b = gwarp >> 12;
    int2 c = cand[gwarp];
    const float4* xr = (const float4*)(xn + (long)gwarp * FEAT_C);
    const float4* s1 = (const float4*)(sn + ((long)(b << 12) + c.x) * FEAT_C);
    const float4* s2 = (const float4*)(sn + ((long)(b << 12) + c.y) * FEAT_C);
    float d1 = 0.f, d2 = 0.f;
#pragma unroll
    for (int i = 0; i < 6; i++) {
        int k = i * 32 + lane;
        float4 xv = xr[k], a = s1[k], bb = s2[k];
        d1 += xv.x * a.x + xv.y * a.y + xv.z * a.z + xv.w * a.w;
        d2 += xv.x * bb.x + xv.y * bb.y + xv.z * bb.z + xv.w * bb.w;
    }
#pragma unroll
    for (int off = 16; off > 0; off >>= 1) {
        d1 += __shfl_xor_sync(0xFFFFFFFF, d1, off);
        d2 += __shfl_xor_sync(0xFFFFFFFF, d2, off);
    }
    if (lane == 0) rowmax[gwarp] = fmaxf(d1, d2);
}

__global__ void loss_kernel(const float* __restrict__ rowmax, float* __restrict__ out) {
    __shared__ float sred[256];
    float s = 0.f;
    for (int i = threadIdx.x; i < BATCH * FEAT_N; i += 256)
        s += 1.0f - rowmax[i];
    sred[threadIdx.x] = s;
    __syncthreads();
    for (int k = 128; k > 0; k >>= 1) {
        if (threadIdx.x < k) sred[threadIdx.x] += sred[threadIdx.x + k];
        __syncthreads();
    }
    if (threadIdx.x == 0) out[0] = sred[0] / (float)(BATCH * FEAT_N);
}

// ---------------------------------------------------------------------------
// Host orchestration
// ---------------------------------------------------------------------------
static void launch_conv_mma(const __half* ih, const __half* il,
                            const __half* wh, const __half* wl, const float* bias,
                            __half* oh, __half* ol,
                            int Cin, int Cout, int H, int W, int inStride, int outStride) {
    dim3 grid(W / 16, H / 8, NBATCH * (Cout / 64));
    conv_mma_kernel<<<grid, 256>>>(ih, il, wh, wl, bias, oh, ol,
                                   Cin, Cout, H, W, inStride, outStride);
}

extern "C" void kernel_launch(void* const* d_in, const int* in_sizes, int n_in,
                              void* d_out, int out_size) {
    const float* outputs = (const float*)d_in[0];
    const float* styles  = (const float*)d_in[1];
    const float* w[7];
    const float* bi[7];
    for (int i = 0; i < 7; i++) {
        w[i]  = (const float*)d_in[2 + 2 * i];
        bi[i] = (const float*)d_in[3 + 2 * i];
    }

    __half *Ah, *Al, *Bh, *Bl, *fh, *fl, *wh, *wl, *xhh;
    float *xn, *rnorm, *rowmax;
    int2* cand;
    cudaGetSymbolAddress((void**)&Ah, g_Ah);
    cudaGetSymbolAddress((void**)&Al, g_Al);
    cudaGetSymbolAddress((void**)&Bh, g_Bh);
    cudaGetSymbolAddress((void**)&Bl, g_Bl);
    cudaGetSymbolAddress((void**)&fh, g_feath);
    cudaGetSymbolAddress((void**)&fl, g_featl);
    cudaGetSymbolAddress((void**)&wh, g_wh);
    cudaGetSymbolAddress((void**)&wl, g_wl);
    cudaGetSymbolAddress((void**)&xn, g_xn);
    cudaGetSymbolAddress((void**)&xhh, g_xh);
    cudaGetSymbolAddress((void**)&rnorm, g_rnorm);
    cudaGetSymbolAddress((void**)&rowmax, g_rowmax);
    cudaGetSymbolAddress((void**)&cand, g_cand);

    // weight fragment prep
    wprep_frag_kernel<<<144, 256>>>(w[1], wh + W12_OFF, wl + W12_OFF, 64, 64);
    wprep_frag_kernel<<<288, 256>>>(w[2], wh + W21_OFF, wl + W21_OFF, 128, 64);
    wprep_frag_kernel<<<576, 256>>>(w[3], wh + W22_OFF, wl + W22_OFF, 128, 128);
    wprep_frag_kernel<<<1152, 256>>>(w[4], wh + W31_OFF, wl + W31_OFF, 256, 128);
    wprep_frag_kernel<<<2304, 256>>>(w[5], wh + W32_OFF, wl + W32_OFF, 256, 256);
    wprep_frag_kernel<<<2304, 256>>>(w[6], wh + W33_OFF, wl + W33_OFF, 256, 256);

    // fused batch-8 feature extraction (outputs: b 0-3, styles: b 4-7)
    conv1_kernel<<<NBATCH * 65536 / 256, 256>>>(outputs, styles, w[0], bi[0], Ah, Al);
    launch_conv_mma(Ah, Al, wh + W12_OFF, wl + W12_OFF, bi[1], Bh, Bl,
                    64, 64, 256, 256, 64, 64);
    maxpool_hl_kernel<<<4096, 256>>>(Bh, Bl, Ah, Al, 64, 256, 256, NBATCH);
    launch_conv_mma(Ah, Al, wh + W21_OFF, wl + W21_OFF, bi[2], Bh, Bl,
                    64, 128, 128, 128, 64, 128);
    launch_conv_mma(Bh, Bl, wh + W22_OFF, wl + W22_OFF, bi[3], Ah, Al,
                    128, 128, 128, 128, 128, 128);
    maxpool_hl_kernel<<<2048, 256>>>(Ah, Al, Bh, Bl, 128, 128, 128, NBATCH);
    launch_conv_mma(Bh, Bl, wh + W31_OFF, wl + W31_OFF, bi[4], fh, fl,
                    128, 256, 64, 64, 128, 768);
    launch_conv_mma(fh, fl, wh + W32_OFF, wl + W32_OFF, bi[5], fh + 256, fl + 256,
                    256, 256, 64, 64, 768, 768);
    launch_conv_mma(fh + 256, fl + 256, wh + W33_OFF, wl + W33_OFF, bi[6],
                    fh + 512, fl + 512, 256, 256, 64, 64, 768, 768);

    norms_nhwc_kernel<<<(NBATCH * FEAT_N * 32 + 255) / 256, 256>>>(fh, fl, rnorm);
    normalize_kernel<<<4096, 256>>>(fh, fl, rnorm, xn, xhh);

    const long soff = (long)BATCH * FEAT_N * FEAT_C;
    dim3 mg(FEAT_N / 128, BATCH);
    maxdot_mma_kernel<<<mg, 256>>>(xhh, xhh + soff, cand);
    rescore_kernel<<<(BATCH * FEAT_N) / 8, 256>>>(xn, xn + soff, cand, rowmax);
    loss_kernel<<<1, 256>>>(rowmax, (float*)d_out);
}